// round 6
// baseline (speedup 1.0000x reference)
#include <cuda_runtime.h>
#include <cuda_bf16.h>

// CRF neg-log-likelihood, GB300 sm_103a.
// One WARP per batch row (64 CTAs x 32 threads). Partition vector lives in
// REGISTERS: lane l<25 owns pair (p[2l],p[2l+1]) as bf162 + two pre-splatted
// copies. Per step: 50 SHFL broadcasts + 50 HFMA2 (lane's column pair),
// bf16 multiply by exp(feat), mask select, rescale by p[0] every 4 steps
// (p[0] splat = the k=0 shuffle, free). Zero smem / zero barriers in the loop.

namespace {
constexpr int NTAG   = 50;
constexpr int TSTART = NTAG - 2;   // 48
constexpr int TSTOP  = NTAG - 1;   // 49
constexpr int BATCH  = 64;
constexpr int SEQ    = 512;
constexpr int NTHR   = 32;
}

__device__ float    g_partial[BATCH];
__device__ unsigned g_ticket = 0;

__device__ __forceinline__ __nv_bfloat162 u2b(unsigned u) {
    return *reinterpret_cast<__nv_bfloat162*>(&u);
}
__device__ __forceinline__ unsigned b2u(__nv_bfloat162 b) {
    return *reinterpret_cast<unsigned*>(&b);
}
// splat low/high bf16 half of a 32-bit reg into both halves (PRMT, alu pipe)
__device__ __forceinline__ unsigned splat_lo(unsigned a) {
    unsigned r; asm("prmt.b32 %0, %1, 0, 0x1010;" : "=r"(r) : "r"(a)); return r;
}
__device__ __forceinline__ unsigned splat_hi(unsigned a) {
    unsigned r; asm("prmt.b32 %0, %1, 0, 0x3232;" : "=r"(r) : "r"(a)); return r;
}
__device__ __forceinline__ float warpSumF(float v) {
#pragma unroll
    for (int o = 16; o > 0; o >>= 1) v += __shfl_xor_sync(0xffffffffu, v, o);
    return v;
}
__device__ __forceinline__ int warpSumI(int v) {
#pragma unroll
    for (int o = 16; o > 0; o >>= 1) v += __shfl_xor_sync(0xffffffffu, v, o);
    return v;
}

// 25 broadcast pairs + 50 HFMA2 into 4 accumulators; returns tree-summed bf162.
// Also exports the k=0 low broadcast (= splat of p[0]) for the rescale.
__device__ __forceinline__ __nv_bfloat162 gemv_pair(
    unsigned sp_lo, unsigned sp_hi,
    const __nv_bfloat162 (&et2)[NTAG],
    unsigned& p0u)
{
    __nv_bfloat162 z  = __floats2bfloat162_rn(0.f, 0.f);
    __nv_bfloat162 a0 = z, a1 = z, a2 = z, a3 = z;
#pragma unroll
    for (int k = 0; k < 25; k++) {
        unsigned blo = __shfl_sync(0xffffffffu, sp_lo, k);
        unsigned bhi = __shfl_sync(0xffffffffu, sp_hi, k);
        if (k == 0) p0u = blo;
        if (k & 1) {
            a2 = __hfma2(u2b(blo), et2[2 * k],     a2);
            a3 = __hfma2(u2b(bhi), et2[2 * k + 1], a3);
        } else {
            a0 = __hfma2(u2b(blo), et2[2 * k],     a0);
            a1 = __hfma2(u2b(bhi), et2[2 * k + 1], a1);
        }
    }
    return __hadd2(__hadd2(a0, a1), __hadd2(a2, a3));
}

// One recursion step. All state in registers; warp-synchronous, no barriers.
template <bool RESCALE>
__device__ __forceinline__ void fwd_step(
    int t, int lc, bool act,
    __nv_bfloat162& p2, unsigned& sp_lo, unsigned& sp_hi,
    const __nv_bfloat162 (&et2)[NTAG],
    __nv_bfloat162& ef2, float2& f1, float2& f2, float2& f3,
    float& offset,
    const float* __restrict__ fb,
    const int*   __restrict__ s_mask)
{
    // prefetch raw feat pair (t+4); exponentiate feat pair (t+1) for next step
    float2 frN = make_float2(0.f, 0.f);
    if ((t + 4) < SEQ) frN = *(const float2*)(fb + (t + 4) * NTAG + 2 * lc);
    __nv_bfloat162 ef_next = __floats2bfloat162_rn(__expf(f1.x), __expf(f1.y));

    const int m = s_mask[t];

    unsigned p0u;
    __nv_bfloat162 s2 = gemv_pair(sp_lo, sp_hi, et2, p0u);
    __nv_bfloat162 q2 = __hmul2(s2, ef2);

    q2 = m ? q2 : p2;                    // masked step: carry previous partition

    if (RESCALE) {
        float p0f = __low2float(u2b(p0u));
        float rp  = __frcp_rn(p0f);
        q2 = __hmul2(q2, __float2bfloat162_rn(rp));
        offset += __logf(p0f);
    }

    p2 = q2;
    unsigned qu = b2u(q2);
    sp_lo = splat_lo(qu);
    sp_hi = splat_hi(qu);

    ef2 = ef_next; f1 = f2; f2 = f3; f3 = frN;
}

__global__ void __launch_bounds__(NTHR, 1)
crf_kernel(const float* __restrict__ feats,
           const int*   __restrict__ mask,
           const int*   __restrict__ tags,
           const float* __restrict__ trans,
           float*       __restrict__ out)
{
    const int b    = blockIdx.x;
    const int l    = threadIdx.x;          // lane
    const bool act = (l < 25);             // lane owns columns 2l, 2l+1
    const int lc   = act ? l : 24;         // clamped for loads

    __shared__ int   s_mask[SEQ];
    __shared__ float s_red;

    const float* fb = feats + (long long)b * SEQ * NTAG;
    const int*   mb = mask  + b * SEQ;
    const int*   tb = tags  + b * SEQ;

    // preload mask bits (int4 x 4 per lane)
#pragma unroll
    for (int t = l * 4; t < SEQ; t += NTHR * 4)
        *(int4*)(s_mask + t) = *(const int4*)(mb + t);

    // exp(transitions) for this lane's column pair, all 50 prev-tags, bf162
    __nv_bfloat162 et2[NTAG];
#pragma unroll
    for (int i = 0; i < NTAG; i++) {
        float e0 = act ? __expf(trans[i * NTAG + 2 * lc])     : 0.f;
        float e1 = act ? __expf(trans[i * NTAG + 2 * lc + 1]) : 0.f;
        et2[i] = __floats2bfloat162_rn(e0, e1);
    }

    // t = 0: normalize by partition0[tag 0] (per-lane computable)
    const float off0   = fb[0] + trans[TSTART * NTAG + 0];
    float       offset = off0;
    float2 fv0 = *(const float2*)(fb + 2 * lc);
    float pa = act ? __expf(fv0.x + trans[TSTART * NTAG + 2 * lc]     - off0) : 0.f;
    float pb = act ? __expf(fv0.y + trans[TSTART * NTAG + 2 * lc + 1] - off0) : 0.f;
    __nv_bfloat162 p2 = __floats2bfloat162_rn(pa, pb);
    unsigned sp_lo = splat_lo(b2u(p2));
    unsigned sp_hi = splat_hi(b2u(p2));

    // feat pipeline: ef2 = exp(feat pair @ t=1); f1..f3 = raw pairs @ t=2..4
    float2 fe1 = *(const float2*)(fb + 1 * NTAG + 2 * lc);
    __nv_bfloat162 ef2 = __floats2bfloat162_rn(__expf(fe1.x), __expf(fe1.y));
    float2 f1 = *(const float2*)(fb + 2 * NTAG + 2 * lc);
    float2 f2 = *(const float2*)(fb + 3 * NTAG + 2 * lc);
    float2 f3 = *(const float2*)(fb + 4 * NTAG + 2 * lc);
    __syncwarp();

    // t = 1..508 in groups of 4 (rescale on 4th); tail 509..511
    for (int t = 1; t + 3 < SEQ; t += 4) {
        fwd_step<false>(t,     lc, act, p2, sp_lo, sp_hi, et2, ef2, f1, f2, f3, offset, fb, s_mask);
        fwd_step<false>(t + 1, lc, act, p2, sp_lo, sp_hi, et2, ef2, f1, f2, f3, offset, fb, s_mask);
        fwd_step<false>(t + 2, lc, act, p2, sp_lo, sp_hi, et2, ef2, f1, f2, f3, offset, fb, s_mask);
        fwd_step<true >(t + 3, lc, act, p2, sp_lo, sp_hi, et2, ef2, f1, f2, f3, offset, fb, s_mask);
    }
    fwd_step<false>(SEQ - 3, lc, act, p2, sp_lo, sp_hi, et2, ef2, f1, f2, f3, offset, fb, s_mask);
    fwd_step<false>(SEQ - 2, lc, act, p2, sp_lo, sp_hi, et2, ef2, f1, f2, f3, offset, fb, s_mask);
    fwd_step<false>(SEQ - 1, lc, act, p2, sp_lo, sp_hi, et2, ef2, f1, f2, f3, offset, fb, s_mask);

    // terminal pseudo-step (no feat, no mask): s2 = P x exp(trans)
    unsigned p0u_dummy;
    __nv_bfloat162 s2 = gemv_pair(sp_lo, sp_hi, et2, p0u_dummy);
    // column TSTOP = 49 = high half of lane 24
    unsigned su = __shfl_sync(0xffffffffu, b2u(s2), 24);
    float fwd = __logf(__high2float(u2b(su))) + offset;

    // ---- gold score (same warp) ----
    float acc = 0.f;
    int   len = 0;
#pragma unroll 4
    for (int t = l; t < SEQ; t += NTHR) {
        int tag  = tb[t];
        int prev = (t == 0) ? TSTART : tb[t - 1];
        int m    = s_mask[t];
        if (m) acc += fb[t * NTAG + tag] + trans[prev * NTAG + tag];
        len += m;
    }
    acc = warpSumF(acc);
    len = warpSumI(len);

    if (l == 0) {
        int   endid = tb[len - 1];
        float gold  = acc + trans[endid * NTAG + TSTOP];
        g_partial[b] = fwd - gold;
        __threadfence();
    }
    __syncwarp();

    // last CTA out: reduce all 64 batch values, reset ticket (graph-replay safe)
    bool last = false;
    if (l == 0) {
        unsigned tk = atomicAdd(&g_ticket, 1u);
        last = (tk == BATCH - 1);
        s_red = last ? 1.f : 0.f;
    }
    __syncwarp();
    if (s_red != 0.f) {
        float v = ((volatile float*)g_partial)[l] + ((volatile float*)g_partial)[l + 32];
        v = warpSumF(v);
        if (l == 0) {
            out[0] = v;
            g_ticket = 0;
        }
    }
}

extern "C" void kernel_launch(void* const* d_in, const int* in_sizes, int n_in,
                              void* d_out, int out_size)
{
    const float* feats = (const float*)d_in[0];
    const int*   mask  = (const int*)d_in[1];
    const int*   tags  = (const int*)d_in[2];
    const float* trans = (const float*)d_in[3];
    float* out = (float*)d_out;

    crf_kernel<<<BATCH, NTHR>>>(feats, mask, tags, trans, out);
}

// round 7
// speedup vs baseline: 1.3670x; 1.3670x over previous
#include <cuda_runtime.h>
#include <cuda_bf16.h>
#include <math_constants.h>

// CRF neg-log-likelihood, GB300 sm_103a.
// 64 CTAs x 64 threads (2 warps; BAR.SYNC nw=2 floor ~7 cyc).
// Linear-space forward recursion, partition bf16 in smem ping-pong, GEMV via
// 25 HFMA2 (thread j owns next-tag j), ALL-bf16 epilogue (PRMT swap + HADD2 +
// HMUL2 + SEL + STS.U16 -- no fp32 on the chain), rescale by p_prev[0] every
// 4 steps. Feat LDG prefetch / expf / mask prefetch moved AFTER the STS so the
// 7 LDS.128 issue immediately after the barrier.

namespace {
constexpr int NTAG   = 50;
constexpr int TSTART = NTAG - 2;   // 48
constexpr int TSTOP  = NTAG - 1;   // 49
constexpr int BATCH  = 64;
constexpr int SEQ    = 512;
constexpr int NTHR   = 64;
constexpr int NPAIR  = 28;         // bf162 pairs (56 slots: 50 + 6 zero pad)
}

__device__ float    g_partial[BATCH];
__device__ unsigned g_ticket = 0;

__device__ __forceinline__ float warpSumF(float v) {
#pragma unroll
    for (int o = 16; o > 0; o >>= 1) v += __shfl_xor_sync(0xffffffffu, v, o);
    return v;
}
__device__ __forceinline__ int warpSumI(int v) {
#pragma unroll
    for (int o = 16; o > 0; o >>= 1) v += __shfl_xor_sync(0xffffffffu, v, o);
    return v;
}
__device__ __forceinline__ __nv_bfloat162 asbf2(float f) {
    return *reinterpret_cast<__nv_bfloat162*>(&f);
}
__device__ __forceinline__ unsigned b2u(__nv_bfloat162 b) {
    return *reinterpret_cast<unsigned*>(&b);
}
__device__ __forceinline__ __nv_bfloat162 u2b(unsigned u) {
    return *reinterpret_cast<__nv_bfloat162*>(&u);
}
// swap 16-bit halves of a 32-bit reg
__device__ __forceinline__ unsigned swap16(unsigned a) {
    unsigned r; asm("prmt.b32 %0, %1, 0, 0x1032;" : "=r"(r) : "r"(a)); return r;
}

// One recursion step. Barrier at the end. m holds mask[t] on entry, mask[t+1] on exit.
template <bool RESCALE>
__device__ __forceinline__ void fwd_step(
    int t, int j, bool act,
    const __nv_bfloat162* __restrict__ src,
    __nv_bfloat162*       __restrict__ dst,
    const __nv_bfloat162 (&et2)[NPAIR],
    unsigned& ef2u, float& fr1, float& fr2, float& fr3,
    unsigned& pju, float& offset, int& m,
    const float* __restrict__ fb,
    const int*   __restrict__ s_mask)
{
    // ---- critical path: loads first ----
    const float4* sp4 = (const float4*)src;
    float4 v0 = sp4[0];
    float4 v1 = sp4[1];
    float4 v2 = sp4[2];
    float4 v3 = sp4[3];
    float4 v4 = sp4[4];
    float4 v5 = sp4[5];
    float4 v6 = sp4[6];

    float p0f = 1.f, rp0 = 1.f;
    if (RESCALE) {
        p0f = __uint_as_float(__float_as_uint(v0.x) << 16);  // low bf16 of pair 0
        rp0 = __frcp_rn(p0f);                                 // MUFU, off-path
    }

    __nv_bfloat162 z  = __floats2bfloat162_rn(0.f, 0.f);
    __nv_bfloat162 a0 = z, a1 = z, a2 = z, a3 = z;

    a0 = __hfma2(asbf2(v0.x), et2[0],  a0);
    a1 = __hfma2(asbf2(v0.y), et2[1],  a1);
    a2 = __hfma2(asbf2(v0.z), et2[2],  a2);
    a3 = __hfma2(asbf2(v0.w), et2[3],  a3);
    a0 = __hfma2(asbf2(v1.x), et2[4],  a0);
    a1 = __hfma2(asbf2(v1.y), et2[5],  a1);
    a2 = __hfma2(asbf2(v1.z), et2[6],  a2);
    a3 = __hfma2(asbf2(v1.w), et2[7],  a3);
    a0 = __hfma2(asbf2(v2.x), et2[8],  a0);
    a1 = __hfma2(asbf2(v2.y), et2[9],  a1);
    a2 = __hfma2(asbf2(v2.z), et2[10], a2);
    a3 = __hfma2(asbf2(v2.w), et2[11], a3);
    a0 = __hfma2(asbf2(v3.x), et2[12], a0);
    a1 = __hfma2(asbf2(v3.y), et2[13], a1);
    a2 = __hfma2(asbf2(v3.z), et2[14], a2);
    a3 = __hfma2(asbf2(v3.w), et2[15], a3);
    a0 = __hfma2(asbf2(v4.x), et2[16], a0);
    a1 = __hfma2(asbf2(v4.y), et2[17], a1);
    a2 = __hfma2(asbf2(v4.z), et2[18], a2);
    a3 = __hfma2(asbf2(v4.w), et2[19], a3);
    a0 = __hfma2(asbf2(v5.x), et2[20], a0);
    a1 = __hfma2(asbf2(v5.y), et2[21], a1);
    a2 = __hfma2(asbf2(v5.z), et2[22], a2);
    a3 = __hfma2(asbf2(v5.w), et2[23], a3);
    a0 = __hfma2(asbf2(v6.x), et2[24], a0);
    a1 = __hfma2(asbf2(v6.y), et2[25], a1);
    a2 = __hfma2(asbf2(v6.z), et2[26], a2);
    a3 = __hfma2(asbf2(v6.w), et2[27], a3);

    a0 = __hadd2(a0, a1);
    a2 = __hadd2(a2, a3);
    a0 = __hadd2(a0, a2);
    // total in BOTH halves: a0 += swap16(a0)
    a0 = __hadd2(a0, u2b(swap16(b2u(a0))));
    // multiply by splatted exp(feat)
    unsigned q2u = b2u(__hmul2(a0, u2b(ef2u)));

    q2u = m ? q2u : pju;                      // masked step: carry previous

    if (RESCALE)
        q2u = b2u(__hmul2(u2b(q2u), __float2bfloat162_rn(rp0)));

    pju = q2u;
    if (act) ((__nv_bfloat16*)dst)[j] = __low2bfloat16(u2b(q2u));  // STS.U16

    // ---- off-path: fills the window before the barrier ----
    m = s_mask[t + 1];                        // mask prefetch (padded array)
    float frN = 0.f;
    if (act && (t + 4) < SEQ) frN = fb[(t + 4) * NTAG + j];
    ef2u = b2u(__float2bfloat162_rn(__expf(fr1)));   // splatted exp(feat t+1)
    fr1 = fr2; fr2 = fr3; fr3 = frN;
    if (RESCALE) offset += __logf(p0f);

    __syncthreads();
}

__global__ void __launch_bounds__(NTHR, 1)
crf_kernel(const float* __restrict__ feats,
           const int*   __restrict__ mask,
           const int*   __restrict__ tags,
           const float* __restrict__ trans,
           float*       __restrict__ out)
{
    const int b    = blockIdx.x;
    const int j    = threadIdx.x;
    const int lane = j & 31;
    const int wid  = j >> 5;
    const bool act = (j < NTAG);

    __shared__ __align__(16) __nv_bfloat162 spA[NPAIR];
    __shared__ __align__(16) __nv_bfloat162 spB[NPAIR];
    __shared__ float s_fwd;
    __shared__ float s_acc[2];
    __shared__ int   s_len[2];
    __shared__ int   s_mask[SEQ + 4];   // +pad so m-prefetch at t=SEQ-1 is in-bounds
    __shared__ bool  s_last;
    __shared__ float s_red2[2];

    const float* fb = feats + (long long)b * SEQ * NTAG;
    const int*   mb = mask  + b * SEQ;
    const int*   tb = tags  + b * SEQ;

    // preload mask bits; zero the pad
    for (int t = j; t < SEQ; t += NTHR) s_mask[t] = mb[t];
    if (j < 4) s_mask[SEQ + j] = 0;

    // exp(transitions) column j as bf162 pairs (thread j owns next-tag j)
    __nv_bfloat162 et2[NPAIR];
#pragma unroll
    for (int k = 0; k < NPAIR; k++) et2[k] = __floats2bfloat162_rn(0.f, 0.f);
    if (act) {
#pragma unroll
        for (int k = 0; k < 25; k++) {
            float e0 = __expf(trans[(2 * k)     * NTAG + j]);
            float e1 = __expf(trans[(2 * k + 1) * NTAG + j]);
            et2[k] = __floats2bfloat162_rn(e0, e1);
        }
    }

    // t = 0: normalize by partition0[tag 0] (per-thread computable)
    const float off0   = fb[0] + trans[TSTART * NTAG + 0];
    float       offset = off0;
    float p0 = act ? __expf(fb[j] + trans[TSTART * NTAG + j] - off0) : 0.f;
    unsigned pju = b2u(__float2bfloat162_rn(p0));   // both halves = p_j
    if (j < 2 * NPAIR) {
        ((__nv_bfloat16*)spA)[j] = __low2bfloat16(u2b(pju));
        ((__nv_bfloat16*)spB)[j] = __float2bfloat16(0.f);  // zero pads once
    }

    // feat pipeline: ef2u = splat(exp(feat(1))); fr1..fr3 = raw feats(2..4)
    unsigned ef2u = b2u(__float2bfloat162_rn(1.f));
    float fr1 = 0.f, fr2 = 0.f, fr3 = 0.f;
    if (act) {
        ef2u = b2u(__float2bfloat162_rn(__expf(fb[1 * NTAG + j])));
        fr1  = fb[2 * NTAG + j];
        fr2  = fb[3 * NTAG + j];
        fr3  = fb[4 * NTAG + j];
    }
    __syncthreads();

    int m = s_mask[1];

    // groups of 4 steps (rescale on 4th), tail 509..511
    for (int t = 1; t + 3 < SEQ; t += 4) {
        fwd_step<false>(t,     j, act, spA, spB, et2, ef2u, fr1, fr2, fr3, pju, offset, m, fb, s_mask);
        fwd_step<false>(t + 1, j, act, spB, spA, et2, ef2u, fr1, fr2, fr3, pju, offset, m, fb, s_mask);
        fwd_step<false>(t + 2, j, act, spA, spB, et2, ef2u, fr1, fr2, fr3, pju, offset, m, fb, s_mask);
        fwd_step<true >(t + 3, j, act, spB, spA, et2, ef2u, fr1, fr2, fr3, pju, offset, m, fb, s_mask);
    }
    fwd_step<false>(SEQ - 3, j, act, spA, spB, et2, ef2u, fr1, fr2, fr3, pju, offset, m, fb, s_mask);
    fwd_step<false>(SEQ - 2, j, act, spB, spA, et2, ef2u, fr1, fr2, fr3, pju, offset, m, fb, s_mask);
    fwd_step<false>(SEQ - 1, j, act, spA, spB, et2, ef2u, fr1, fr2, fr3, pju, offset, m, fb, s_mask);
    // final partition lives in spB

    // terminal: forward = log( sum_i p[i] * exp(trans[i,STOP]) ) + offset
    if (j == TSTOP) {
        const float4* sp4 = (const float4*)spB;
        __nv_bfloat162 z  = __floats2bfloat162_rn(0.f, 0.f);
        __nv_bfloat162 a0 = z, a1 = z, a2 = z, a3 = z;
#pragma unroll
        for (int k = 0; k < 7; k++) {
            float4 v = sp4[k];
            a0 = __hfma2(asbf2(v.x), et2[4 * k + 0], a0);
            a1 = __hfma2(asbf2(v.y), et2[4 * k + 1], a1);
            a2 = __hfma2(asbf2(v.z), et2[4 * k + 2], a2);
            a3 = __hfma2(asbf2(v.w), et2[4 * k + 3], a3);
        }
        a0 = __hadd2(a0, a1);
        a2 = __hadd2(a2, a3);
        a0 = __hadd2(a0, a2);
        float2 sf = __bfloat1622float2(a0);
        s_fwd = __logf(sf.x + sf.y) + offset;
    }

    // ---- gold score (all 64 threads, epilogue) ----
    float acc = 0.f;
    int   len = 0;
#pragma unroll
    for (int t = j; t < SEQ; t += NTHR) {
        int tag  = tb[t];
        int prev = (t == 0) ? TSTART : tb[t - 1];
        int mm   = s_mask[t];
        if (mm) acc += fb[t * NTAG + tag] + trans[prev * NTAG + tag];
        len += mm;
    }
    acc = warpSumF(acc);
    len = warpSumI(len);
    if (lane == 0) { s_acc[wid] = acc; s_len[wid] = len; }
    __syncthreads();

    if (j == 0) {
        int   L     = s_len[0] + s_len[1];
        int   endid = tb[L - 1];
        float gold  = s_acc[0] + s_acc[1] + trans[endid * NTAG + TSTOP];
        g_partial[b] = s_fwd - gold;
        __threadfence();
        unsigned tk = atomicAdd(&g_ticket, 1u);
        s_last = (tk == BATCH - 1);
    }
    __syncthreads();

    // last CTA out: reduce all 64 batch values, reset ticket (graph-replay safe)
    if (s_last) {
        float v = ((volatile float*)g_partial)[j];
        v = warpSumF(v);
        if (lane == 0) s_red2[wid] = v;
        __syncthreads();
        if (j == 0) {
            out[0] = s_red2[0] + s_red2[1];
            g_ticket = 0;
        }
    }
}

extern "C" void kernel_launch(void* const* d_in, const int* in_sizes, int n_in,
                              void* d_out, int out_size)
{
    const float* feats = (const float*)d_in[0];
    const int*   mask  = (const int*)d_in[1];
    const int*   tags  = (const int*)d_in[2];
    const float* trans = (const float*)d_in[3];
    float* out = (float*)d_out;

    crf_kernel<<<BATCH, NTHR>>>(feats, mask, tags, trans, out);
}

// round 8
// speedup vs baseline: 1.3796x; 1.0093x over previous
#include <cuda_runtime.h>
#include <cuda_bf16.h>
#include <math_constants.h>

// CRF neg-log-likelihood, GB300 sm_103a.
// 64 CTAs x 64 threads. Prologue precomputes exp(feats) for the whole row into
// dynamic smem (splatted bf162, 512x52 u32 = 106KB; 1 CTA/SM so occupancy is
// moot). Main loop: BAR -> 7 LDS.128 -> 25 HFMA2 + tree -> HMUL2 -> SEL ->
// STS.U16. No LDG, no MUFU, no register pipeline inside the loop. Rescale by
// p_prev[0] every 4 steps. Gold score epilogue; last CTA reduces the batch.

namespace {
constexpr int NTAG   = 50;
constexpr int TSTART = NTAG - 2;   // 48
constexpr int TSTOP  = NTAG - 1;   // 49
constexpr int BATCH  = 64;
constexpr int SEQ    = 512;
constexpr int NTHR   = 64;
constexpr int NPAIR  = 28;         // bf162 pairs (56 slots: 50 + 6 zero pad)
constexpr int EFW    = 52;         // s_ef row stride (u32)
// dynamic smem: s_ef[(SEQ+1)*EFW] u32, then s_mask[SEQ+4] int
constexpr int SMEM_EF_WORDS   = (SEQ + 1) * EFW;
constexpr int SMEM_MASK_WORDS = SEQ + 4;
constexpr int SMEM_BYTES = (SMEM_EF_WORDS + SMEM_MASK_WORDS) * 4;
}

__device__ float    g_partial[BATCH];
__device__ unsigned g_ticket = 0;

__device__ __forceinline__ float warpSumF(float v) {
#pragma unroll
    for (int o = 16; o > 0; o >>= 1) v += __shfl_xor_sync(0xffffffffu, v, o);
    return v;
}
__device__ __forceinline__ int warpSumI(int v) {
#pragma unroll
    for (int o = 16; o > 0; o >>= 1) v += __shfl_xor_sync(0xffffffffu, v, o);
    return v;
}
__device__ __forceinline__ __nv_bfloat162 asbf2(float f) {
    return *reinterpret_cast<__nv_bfloat162*>(&f);
}
__device__ __forceinline__ unsigned b2u(__nv_bfloat162 b) {
    return *reinterpret_cast<unsigned*>(&b);
}
__device__ __forceinline__ __nv_bfloat162 u2b(unsigned u) {
    return *reinterpret_cast<__nv_bfloat162*>(&u);
}
__device__ __forceinline__ unsigned swap16(unsigned a) {
    unsigned r; asm("prmt.b32 %0, %1, 0, 0x1032;" : "=r"(r) : "r"(a)); return r;
}
// splat bf16(x) into both halves of a u32
__device__ __forceinline__ unsigned splatbf(float x) {
    return b2u(__float2bfloat162_rn(x));
}

// One recursion step. Everything needed is already in smem/registers.
// On entry: m = mask[t], efu = splat(exp(feat[t])). On exit: prefetched t+1.
template <bool RESCALE>
__device__ __forceinline__ void fwd_step(
    int t, int j, bool act,
    const __nv_bfloat162* __restrict__ src,
    __nv_bfloat162*       __restrict__ dst,
    const __nv_bfloat162 (&et2)[NPAIR],
    unsigned& efu, int& m, unsigned& pju, float& offset,
    const unsigned* __restrict__ s_ef,
    const int*      __restrict__ s_mask)
{
    // critical path: partition loads first (broadcast, conflict-free)
    const float4* sp4 = (const float4*)src;
    float4 v0 = sp4[0];
    float4 v1 = sp4[1];
    float4 v2 = sp4[2];
    float4 v3 = sp4[3];
    float4 v4 = sp4[4];
    float4 v5 = sp4[5];
    float4 v6 = sp4[6];

    float p0f = 1.f, rp0 = 1.f;
    if (RESCALE) {
        p0f = __uint_as_float(__float_as_uint(v0.x) << 16);  // low bf16 of pair 0
        rp0 = __frcp_rn(p0f);                                 // MUFU, off-path
    }

    __nv_bfloat162 z  = __floats2bfloat162_rn(0.f, 0.f);
    __nv_bfloat162 a0 = z, a1 = z, a2 = z, a3 = z;

    a0 = __hfma2(asbf2(v0.x), et2[0],  a0);
    a1 = __hfma2(asbf2(v0.y), et2[1],  a1);
    a2 = __hfma2(asbf2(v0.z), et2[2],  a2);
    a3 = __hfma2(asbf2(v0.w), et2[3],  a3);
    a0 = __hfma2(asbf2(v1.x), et2[4],  a0);
    a1 = __hfma2(asbf2(v1.y), et2[5],  a1);
    a2 = __hfma2(asbf2(v1.z), et2[6],  a2);
    a3 = __hfma2(asbf2(v1.w), et2[7],  a3);
    a0 = __hfma2(asbf2(v2.x), et2[8],  a0);
    a1 = __hfma2(asbf2(v2.y), et2[9],  a1);
    a2 = __hfma2(asbf2(v2.z), et2[10], a2);
    a3 = __hfma2(asbf2(v2.w), et2[11], a3);
    a0 = __hfma2(asbf2(v3.x), et2[12], a0);
    a1 = __hfma2(asbf2(v3.y), et2[13], a1);
    a2 = __hfma2(asbf2(v3.z), et2[14], a2);
    a3 = __hfma2(asbf2(v3.w), et2[15], a3);
    a0 = __hfma2(asbf2(v4.x), et2[16], a0);
    a1 = __hfma2(asbf2(v4.y), et2[17], a1);
    a2 = __hfma2(asbf2(v4.z), et2[18], a2);
    a3 = __hfma2(asbf2(v4.w), et2[19], a3);
    a0 = __hfma2(asbf2(v5.x), et2[20], a0);
    a1 = __hfma2(asbf2(v5.y), et2[21], a1);
    a2 = __hfma2(asbf2(v5.z), et2[22], a2);
    a3 = __hfma2(asbf2(v5.w), et2[23], a3);
    a0 = __hfma2(asbf2(v6.x), et2[24], a0);
    a1 = __hfma2(asbf2(v6.y), et2[25], a1);
    a2 = __hfma2(asbf2(v6.z), et2[26], a2);
    a3 = __hfma2(asbf2(v6.w), et2[27], a3);

    a0 = __hadd2(a0, a1);
    a2 = __hadd2(a2, a3);
    a0 = __hadd2(a0, a2);
    a0 = __hadd2(a0, u2b(swap16(b2u(a0))));     // total in both halves
    unsigned q2u = b2u(__hmul2(a0, u2b(efu)));  // * exp(feat[t])

    q2u = m ? q2u : pju;                        // masked: carry previous

    if (RESCALE)
        q2u = b2u(__hmul2(u2b(q2u), __float2bfloat162_rn(rp0)));

    pju = q2u;
    if (act) ((__nv_bfloat16*)dst)[j] = __low2bfloat16(u2b(q2u));  // STS.U16

    // off-path prefetches for step t+1 (smem only, cheap)
    efu = s_ef[(t + 1) * EFW + j];
    m   = s_mask[t + 1];
    if (RESCALE) offset += __logf(p0f);

    __syncthreads();
}

__global__ void __launch_bounds__(NTHR, 1)
crf_kernel(const float* __restrict__ feats,
           const int*   __restrict__ mask,
           const int*   __restrict__ tags,
           const float* __restrict__ trans,
           float*       __restrict__ out)
{
    const int b    = blockIdx.x;
    const int j    = threadIdx.x;
    const int lane = j & 31;
    const int wid  = j >> 5;
    const bool act = (j < NTAG);

    extern __shared__ unsigned dyn[];
    unsigned* s_ef   = dyn;                         // [(SEQ+1)][EFW]
    int*      s_mask = (int*)(dyn + SMEM_EF_WORDS); // [SEQ+4]

    __shared__ __align__(16) __nv_bfloat162 spA[NPAIR];
    __shared__ __align__(16) __nv_bfloat162 spB[NPAIR];
    __shared__ float s_fwd;
    __shared__ float s_acc[2];
    __shared__ int   s_len[2];
    __shared__ bool  s_last;
    __shared__ float s_red2[2];

    const float* fb = feats + (long long)b * SEQ * NTAG;
    const int*   mb = mask  + b * SEQ;
    const int*   tb = tags  + b * SEQ;

    // ---- prologue: mask bits + exp(feats) for the whole row into smem ----
    for (int t = j; t < SEQ; t += NTHR) s_mask[t] = mb[t];
    if (j < 4) s_mask[SEQ + j] = 0;

    {
        const float4* f4 = (const float4*)fb;       // SEQ*NTAG/4 = 6400 float4
        for (int idx = j; idx < SEQ * NTAG / 4; idx += NTHR) {
            float4 v = f4[idx];
            int e = idx * 4;
            int t0 = e / NTAG,        c0 = e - t0 * NTAG;
            int t1 = (e + 1) / NTAG,  c1 = (e + 1) - t1 * NTAG;
            int t2 = (e + 2) / NTAG,  c2 = (e + 2) - t2 * NTAG;
            int t3 = (e + 3) / NTAG,  c3 = (e + 3) - t3 * NTAG;
            s_ef[t0 * EFW + c0] = splatbf(__expf(v.x));
            s_ef[t1 * EFW + c1] = splatbf(__expf(v.y));
            s_ef[t2 * EFW + c2] = splatbf(__expf(v.z));
            s_ef[t3 * EFW + c3] = splatbf(__expf(v.w));
        }
    }

    // exp(transitions) column j as bf162 pairs (thread j owns next-tag j)
    __nv_bfloat162 et2[NPAIR];
#pragma unroll
    for (int k = 0; k < NPAIR; k++) et2[k] = __floats2bfloat162_rn(0.f, 0.f);
    if (act) {
#pragma unroll
        for (int k = 0; k < 25; k++) {
            float e0 = __expf(trans[(2 * k)     * NTAG + j]);
            float e1 = __expf(trans[(2 * k + 1) * NTAG + j]);
            et2[k] = __floats2bfloat162_rn(e0, e1);
        }
    }

    // t = 0: normalize by partition0[tag 0] (per-thread computable)
    const float off0   = fb[0] + trans[TSTART * NTAG + 0];
    float       offset = off0;
    float p0 = act ? __expf(fb[j] + trans[TSTART * NTAG + j] - off0) : 0.f;
    unsigned pju = splatbf(p0);
    if (j < 2 * NPAIR) {
        ((__nv_bfloat16*)spA)[j] = __low2bfloat16(u2b(pju));
        ((__nv_bfloat16*)spB)[j] = __float2bfloat16(0.f);  // zero pads once
    }
    __syncthreads();

    unsigned efu = s_ef[1 * EFW + j];   // splat(exp(feat[1]))
    int      m   = s_mask[1];

    // groups of 4 steps (rescale on 4th), tail 509..511
    for (int t = 1; t + 3 < SEQ; t += 4) {
        fwd_step<false>(t,     j, act, spA, spB, et2, efu, m, pju, offset, s_ef, s_mask);
        fwd_step<false>(t + 1, j, act, spB, spA, et2, efu, m, pju, offset, s_ef, s_mask);
        fwd_step<false>(t + 2, j, act, spA, spB, et2, efu, m, pju, offset, s_ef, s_mask);
        fwd_step<true >(t + 3, j, act, spB, spA, et2, efu, m, pju, offset, s_ef, s_mask);
    }
    fwd_step<false>(SEQ - 3, j, act, spA, spB, et2, efu, m, pju, offset, s_ef, s_mask);
    fwd_step<false>(SEQ - 2, j, act, spB, spA, et2, efu, m, pju, offset, s_ef, s_mask);
    fwd_step<false>(SEQ - 1, j, act, spA, spB, et2, efu, m, pju, offset, s_ef, s_mask);
    // final partition lives in spB

    // terminal: forward = log( sum_i p[i] * exp(trans[i,STOP]) ) + offset
    if (j == TSTOP) {
        const float4* sp4 = (const float4*)spB;
        __nv_bfloat162 z  = __floats2bfloat162_rn(0.f, 0.f);
        __nv_bfloat162 a0 = z, a1 = z, a2 = z, a3 = z;
#pragma unroll
        for (int k = 0; k < 7; k++) {
            float4 v = sp4[k];
            a0 = __hfma2(asbf2(v.x), et2[4 * k + 0], a0);
            a1 = __hfma2(asbf2(v.y), et2[4 * k + 1], a1);
            a2 = __hfma2(asbf2(v.z), et2[4 * k + 2], a2);
            a3 = __hfma2(asbf2(v.w), et2[4 * k + 3], a3);
        }
        a0 = __hadd2(a0, a1);
        a2 = __hadd2(a2, a3);
        a0 = __hadd2(a0, a2);
        float2 sf = __bfloat1622float2(a0);
        s_fwd = __logf(sf.x + sf.y) + offset;
    }

    // ---- gold score (all 64 threads) ----
    float acc = 0.f;
    int   len = 0;
#pragma unroll
    for (int t = j; t < SEQ; t += NTHR) {
        int tag  = tb[t];
        int prev = (t == 0) ? TSTART : tb[t - 1];
        int mm   = s_mask[t];
        if (mm) acc += fb[t * NTAG + tag] + trans[prev * NTAG + tag];
        len += mm;
    }
    acc = warpSumF(acc);
    len = warpSumI(len);
    if (lane == 0) { s_acc[wid] = acc; s_len[wid] = len; }
    __syncthreads();

    if (j == 0) {
        int   L     = s_len[0] + s_len[1];
        int   endid = tb[L - 1];
        float gold  = s_acc[0] + s_acc[1] + trans[endid * NTAG + TSTOP];
        g_partial[b] = s_fwd - gold;
        __threadfence();
        unsigned tk = atomicAdd(&g_ticket, 1u);
        s_last = (tk == BATCH - 1);
    }
    __syncthreads();

    // last CTA out: reduce all 64 batch values, reset ticket (graph-replay safe)
    if (s_last) {
        float v = ((volatile float*)g_partial)[j];
        v = warpSumF(v);
        if (lane == 0) s_red2[wid] = v;
        __syncthreads();
        if (j == 0) {
            out[0] = s_red2[0] + s_red2[1];
            g_ticket = 0;
        }
    }
}

extern "C" void kernel_launch(void* const* d_in, const int* in_sizes, int n_in,
                              void* d_out, int out_size)
{
    const float* feats = (const float*)d_in[0];
    const int*   mask  = (const int*)d_in[1];
    const int*   tags  = (const int*)d_in[2];
    const float* trans = (const float*)d_in[3];
    float* out = (float*)d_out;

    cudaFuncSetAttribute(crf_kernel,
                         cudaFuncAttributeMaxDynamicSharedMemorySize, SMEM_BYTES);
    crf_kernel<<<BATCH, NTHR, SMEM_BYTES>>>(feats, mask, tags, trans, out);
}